// round 13
// baseline (speedup 1.0000x reference)
#include <cuda_runtime.h>
#include <cuda_fp16.h>
#include <cstdint>

#define N_NODES 2048
#define FDIM 256
#define HID 64
#define TEMPLATE 10
#define RPB 16

// -------- scratch (static device globals; no allocation) --------
__device__ float g_h3[FDIM];
__device__ float g_ha[HID];                  // h3 @ ew1[:256] + eb1  (per k)
__device__ float g_hb[HID];                  // h3 @ ew1[256:]        (per k)
__device__ float g_paT[HID * N_NODES];       // [k][node] 0.1*noise@ew1a (cols 0-9 zero)
__device__ float g_pbT[HID * N_NODES];       // [k][node] 0.1*noise@ew1b (cols 0-9 zero)

__device__ __forceinline__ float sigmoid_fast(float x) {
    float t;
    asm("tanh.approx.f32 %0, %1;" : "=f"(t) : "f"(0.5f * x));
    return fmaf(0.5f, t, 0.5f);
}

// =====================================================================
// Merged kernel: block 0 = GCN with smem-staged weights; blocks 1..128 =
// noise GEMM (0.1*noise @ ew1), 16 rows each -> 129 blocks = ONE wave.
// =====================================================================
#define SMEM_FLOATS 41600
#define SMEM_BYTES  (SMEM_FLOATS * 4)
#define TSTRIDE 20    // 80B row: 16B-aligned for LDS.128
#define PSTRIDE 129   // padded part row: conflict-free strided reduce

extern __shared__ float sm[];

__global__ __launch_bounds__(1024) void merged_kernel(
        const float* __restrict__ cf,  const int* __restrict__ sel,
        const float* __restrict__ w1, const float* __restrict__ b1,
        const float* __restrict__ w2, const float* __restrict__ b2,
        const float* __restrict__ w3, const float* __restrict__ b3,
        const float* __restrict__ noise,
        const float* __restrict__ ew1,
        float* __restrict__ trig_out) {
    int t = threadIdx.x;  // 0..1023
    int b = blockIdx.x;

    if (b == 0) {
        // ================= GCN block =================
        float* w1s   = sm;
        float* w2s   = sm + 16384;
        float* w3s   = sm + 20480;
        float* proto = sm + 36864;
        float* red   = sm + 37120;
        float* h1    = sm + 41216;
        float* h2    = sm + 41280;
        float* h3s   = sm + 41344;

        int sidx[TEMPLATE];
        #pragma unroll
        for (int q = 0; q < TEMPLATE; q++) sidx[q] = sel[q];

        // stream all weights to smem (coalesced float4)
        #pragma unroll
        for (int i = 0; i < 4; i++) {
            int idx = t + i * 1024;
            ((float4*)w1s)[idx] = ((const float4*)w1)[idx];
        }
        ((float4*)w2s)[t] = ((const float4*)w2)[t];
        #pragma unroll
        for (int i = 0; i < 4; i++) {
            int idx = t + i * 1024;
            ((float4*)w3s)[idx] = ((const float4*)w3)[idx];
        }

        if (t < FDIM) {
            float s = 0.f;
            #pragma unroll
            for (int q = 0; q < TEMPLATE; q++)
                s += cf[(size_t)sidx[q] * FDIM + t];
            proto[t] = s * (1.0f / TEMPLATE);
        }
        __syncthreads();

        int o1 = t & 63, kq1 = t >> 6;   // 16 chunks

        // layer1: 256 -> 64
        {
            float a0 = 0.f, a1 = 0.f, a2 = 0.f, a3 = 0.f;
            int kb = kq1 * 16;
            #pragma unroll
            for (int kk = 0; kk < 16; kk += 4) {
                a0 = fmaf(proto[kb+kk],   w1s[(kb+kk)  *HID + o1], a0);
                a1 = fmaf(proto[kb+kk+1], w1s[(kb+kk+1)*HID + o1], a1);
                a2 = fmaf(proto[kb+kk+2], w1s[(kb+kk+2)*HID + o1], a2);
                a3 = fmaf(proto[kb+kk+3], w1s[(kb+kk+3)*HID + o1], a3);
            }
            red[kq1 * 64 + o1] = (a0 + a1) + (a2 + a3);
        }
        __syncthreads();
        if (t < HID) {
            float s = b1[t];
            #pragma unroll
            for (int c = 0; c < 16; c++) s += red[c * 64 + t];
            h1[t] = fmaxf(s, 0.f);
        }
        __syncthreads();

        // layer2: 64 -> 64
        {
            int kb = kq1 * 4;
            float a0 = fmaf(h1[kb],   w2s[(kb)  *HID + o1], 0.f);
            float a1 = fmaf(h1[kb+1], w2s[(kb+1)*HID + o1], 0.f);
            a0 = fmaf(h1[kb+2], w2s[(kb+2)*HID + o1], a0);
            a1 = fmaf(h1[kb+3], w2s[(kb+3)*HID + o1], a1);
            red[kq1 * 64 + o1] = a0 + a1;
        }
        __syncthreads();
        if (t < HID) {
            float s = b2[t];
            #pragma unroll
            for (int c = 0; c < 16; c++) s += red[c * 64 + t];
            h2[t] = fmaxf(s, 0.f);
        }
        __syncthreads();

        // layer3: 64 -> 256
        {
            int o3 = t & 255, kh3 = t >> 8;
            int kb = kh3 * 16;
            float a0 = 0.f, a1 = 0.f, a2 = 0.f, a3 = 0.f;
            #pragma unroll
            for (int kk = 0; kk < 16; kk += 4) {
                a0 = fmaf(h2[kb+kk],   w3s[(kb+kk)  *FDIM + o3], a0);
                a1 = fmaf(h2[kb+kk+1], w3s[(kb+kk+1)*FDIM + o3], a1);
                a2 = fmaf(h2[kb+kk+2], w3s[(kb+kk+2)*FDIM + o3], a2);
                a3 = fmaf(h2[kb+kk+3], w3s[(kb+kk+3)*FDIM + o3], a3);
            }
            red[kh3 * 256 + o3] = (a0 + a1) + (a2 + a3);
        }
        __syncthreads();
        if (t < FDIM) {
            float a = red[t] + red[256 + t] + red[512 + t] + red[768 + t] + b3[t];
            float v = 1.0f / (1.0f + __expf(-a));
            h3s[t] = v;
            g_h3[t] = v;
            #pragma unroll
            for (int r = 0; r < TEMPLATE; r++)
                trig_out[(size_t)r * FDIM + t] = v;
        }
        // zero paT/pbT columns 0..9 (all 64 k rows)
        if (t < HID * TEMPLATE) {
            int k = t / TEMPLATE, node = t % TEMPLATE;
            g_paT[(size_t)k * N_NODES + node] = 0.f;
            g_pbT[(size_t)k * N_NODES + node] = 0.f;
        }
        return;
    }

    // ================= noise GEMM blocks (16 rows each) =================
    float* tst  = sm;                       // [256][TSTRIDE]
    float* part = sm + FDIM * TSTRIDE;      // [8][16][PSTRIDE]
    int r0 = TEMPLATE + (b - 1) * RPB;

    // --- force-prefetch the 32 strided ew1 weights NOW (asm = un-sinkable).
    // Their ~L2 latency is absorbed by the noise prologue + barrier below.
    int o = t & 127, c = t >> 7;
    int half = o >> 6, oc = o & 63;
    const float* w = ew1 + ((size_t)half * FDIM + c * 32) * HID + oc;
    float wv[32];
    #pragma unroll
    for (int u = 0; u < 32; u++) {
        asm volatile("ld.global.nc.f32 %0, [%1];"
                     : "=f"(wv[u]) : "l"(w + (size_t)u * HID));
    }

    // prologue: load 0.1*noise (transposed into tst), write trig noise rows
    {
        int k = t & 255, g = t >> 8;        // g in 0..3 -> rows 4g..4g+3
        #pragma unroll
        for (int rr2 = 0; rr2 < 4; rr2++) {
            int rr = 4 * g + rr2;
            int r = r0 + rr;
            if (r < N_NODES) {
                float v = 0.1f * noise[(size_t)(r - TEMPLATE) * FDIM + k];
                tst[k * TSTRIDE + rr] = v;
                trig_out[(size_t)r * FDIM + k] = v;
            } else {
                tst[k * TSTRIDE + rr] = 0.f;
            }
        }
    }
    __syncthreads();

    // GEMM: weights already in registers; pure FFMA + broadcast LDS.128
    {
        const float* tb = tst + (c * 32) * TSTRIDE;

        float acc[RPB];
        #pragma unroll
        for (int rr = 0; rr < RPB; rr++) acc[rr] = 0.f;

        #pragma unroll 4
        for (int kk = 0; kk < 32; kk++) {
            float wu = wv[kk];
            const float* row = tb + kk * TSTRIDE;
            float4 rA = *(const float4*)(row);
            float4 rB = *(const float4*)(row + 4);
            float4 rC = *(const float4*)(row + 8);
            float4 rD = *(const float4*)(row + 12);
            acc[0]  = fmaf(rA.x, wu, acc[0]);
            acc[1]  = fmaf(rA.y, wu, acc[1]);
            acc[2]  = fmaf(rA.z, wu, acc[2]);
            acc[3]  = fmaf(rA.w, wu, acc[3]);
            acc[4]  = fmaf(rB.x, wu, acc[4]);
            acc[5]  = fmaf(rB.y, wu, acc[5]);
            acc[6]  = fmaf(rB.z, wu, acc[6]);
            acc[7]  = fmaf(rB.w, wu, acc[7]);
            acc[8]  = fmaf(rC.x, wu, acc[8]);
            acc[9]  = fmaf(rC.y, wu, acc[9]);
            acc[10] = fmaf(rC.z, wu, acc[10]);
            acc[11] = fmaf(rC.w, wu, acc[11]);
            acc[12] = fmaf(rD.x, wu, acc[12]);
            acc[13] = fmaf(rD.y, wu, acc[13]);
            acc[14] = fmaf(rD.z, wu, acc[14]);
            acc[15] = fmaf(rD.w, wu, acc[15]);
        }
        #pragma unroll
        for (int rr = 0; rr < RPB; rr++)
            part[(c * RPB + rr) * PSTRIDE + o] = acc[rr];
    }
    __syncthreads();

    // reduce 8 chunks; TRANSPOSED store to g_paT/g_pbT[k][node]
    {
        #pragma unroll
        for (int u = 0; u < 2; u++) {
            int idx = t + u * 1024;
            int rr = idx & 15, oo = idx >> 4;   // lanes vary rr -> node-contig
            int r = r0 + rr;
            if (r < N_NODES) {
                float s = 0.f;
                #pragma unroll
                for (int cc = 0; cc < 8; cc++)
                    s += part[(cc * RPB + rr) * PSTRIDE + oo];
                int hh = oo >> 6, occ = oo & 63;
                if (hh == 0) g_paT[(size_t)occ * N_NODES + r] = s;
                else         g_pbT[(size_t)occ * N_NODES + r] = s;
            }
        }
    }
}

// =====================================================================
// gemv_hab: ha = h3 @ ew1[:256] + eb1 ; hb = h3 @ ew1[256:]
// =====================================================================
__global__ __launch_bounds__(256) void gemv_hab(
        const float* __restrict__ ew1, const float* __restrict__ eb1) {
    __shared__ float red[8];
    int b = blockIdx.x;            // 0..127
    int half = b >> 6, oc = b & 63;
    int t = threadIdx.x;           // 0..255

    float v = g_h3[t] * ew1[((size_t)(half * FDIM + t)) * HID + oc];
    #pragma unroll
    for (int off = 16; off > 0; off >>= 1)
        v += __shfl_xor_sync(0xffffffffu, v, off);
    if ((t & 31) == 0) red[t >> 5] = v;
    __syncthreads();
    if (t == 0) {
        float s = red[0] + red[1] + red[2] + red[3] +
                  red[4] + red[5] + red[6] + red[7];
        if (half == 0) g_ha[oc] = s + eb1[oc];
        else           g_hb[oc] = s;
    }
}

// =====================================================================
// Edge kernel (fp16x2, pre-duplicated a): blocks 0..527 = tiles;
// blocks 528..543 = trig fixup. 256 threads, per-thread 4i x 4j.
// =====================================================================
#define TILE 64
#define HPAD 72                       // half-row stride for b tile
#define NT   (N_NODES / TILE)         // 32
#define NTILES (NT * (NT + 1) / 2)    // 528
#define NFIX 16

__global__ __launch_bounds__(256) void edge_kernel(const float* __restrict__ ew2,
                                                   const float* __restrict__ eb2,
                                                   float* __restrict__ trig_out,
                                                   float* __restrict__ out) {
    int m = blockIdx.x;
    int tid = threadIdx.x;

    if (m >= NTILES) {
        // -------- trig fixup: trig[10:][:] += h3 (float4) --------
        int f = m - NTILES;                                  // 0..15
        const int total4 = (N_NODES - TEMPLATE) * FDIM / 4;  // 130432
        const int per = (total4 + NFIX - 1) / NFIX;
        int s = f * per;
        int e = s + per; if (e > total4) e = total4;
        float4* base = (float4*)(trig_out + (size_t)TEMPLATE * FDIM);
        for (int i = s + tid; i < e; i += 256) {
            int c4 = i & 63;
            float4 h = __ldg((const float4*)&g_h3[c4 * 4]);
            float4 v = base[i];
            v.x += h.x; v.y += h.y; v.z += h.z; v.w += h.w;
            base[i] = v;
        }
        return;
    }

    // decode (bi, bj) with bj >= bi from m
    int bi = (int)(32.5f - sqrtf(32.5f * 32.5f - 2.0f * (float)m));
    while (bi * NT - ((bi * (bi - 1)) >> 1) > m) bi--;
    while ((bi + 1) * NT - (((bi + 1) * bi) >> 1) <= m) bi++;
    int bj = bi + (m - (bi * NT - ((bi * (bi - 1)) >> 1)));

    __shared__ __half2 pah2[HID][TILE];   // [k][i] = (a_i, a_i), 16KB
    __shared__ __half  pbh[HID][HPAD];    // [k][j], 9.2KB
    __shared__ __half2 w2h[HID];          // (w,w) pairs

    // tile load: convert float [k][node] to half; a stored pre-duplicated
    {
        const float* paG = g_paT + (size_t)bi * TILE;
        const float* pbG = g_pbT + (size_t)bj * TILE;
        #pragma unroll
        for (int it = 0; it < 4; it++) {
            int idx = tid + it * 256;     // 1024 slots: k = idx>>4, c4
            int k = idx >> 4;
            int c4 = (idx & 15) << 2;
            float hav = __ldg(&g_ha[k]);
            float hbv = __ldg(&g_hb[k]);
            float4 va = *(const float4*)(paG + (size_t)k * N_NODES + c4);
            pah2[k][c4]     = __float2half2_rn(va.x + hav);
            pah2[k][c4 + 1] = __float2half2_rn(va.y + hav);
            pah2[k][c4 + 2] = __float2half2_rn(va.z + hav);
            pah2[k][c4 + 3] = __float2half2_rn(va.w + hav);
            float4 vb = *(const float4*)(pbG + (size_t)k * N_NODES + c4);
            __half2 pb01 = __floats2half2_rn(vb.x + hbv, vb.y + hbv);
            __half2 pb23 = __floats2half2_rn(vb.z + hbv, vb.w + hbv);
            *(__half2*)&pbh[k][c4]     = pb01;
            *(__half2*)&pbh[k][c4 + 2] = pb23;
        }
        if (tid < HID) w2h[tid] = __float2half2_rn(ew2[tid]);
    }
    float c0 = eb2[0];
    __syncthreads();

    int tx = tid & 15;   // j-group: j = 4*tx + (0..3)
    int ty = tid >> 4;   // i-group: i = 4*ty + (0..3)

    const __half2 zero2 = __float2half2_rn(0.0f);
    // acc[group][i][jp]: 4 interleaved 16-term fp16 partial sums
    __half2 acc[4][4][2];
    #pragma unroll
    for (int g = 0; g < 4; g++)
        #pragma unroll
        for (int i = 0; i < 4; i++) {
            acc[g][i][0] = zero2;
            acc[g][i][1] = zero2;
        }

    #pragma unroll 4
    for (int k = 0; k < HID; k++) {
        int g = k & 3;
        __half2 wk = w2h[k];
        const __half2* ap = &pah2[k][4 * ty];   // 16B-aligned -> LDS.128
        __half2 ad0 = ap[0], ad1 = ap[1], ad2 = ap[2], ad3 = ap[3];
        const __half2* bp = (const __half2*)&pbh[k][4 * tx];
        __half2 b01 = bp[0], b23 = bp[1];
        #pragma unroll
        for (int i = 0; i < 4; i++) {
            __half2 ai = (i == 0) ? ad0 : (i == 1) ? ad1 : (i == 2) ? ad2 : ad3;
            __half2 s0 = __hmax2(__hadd2(ai, b01), zero2);
            __half2 s1 = __hmax2(__hadd2(ai, b23), zero2);
            acc[g][i][0] = __hfma2(s0, wk, acc[g][i][0]);
            acc[g][i][1] = __hfma2(s1, wk, acc[g][i][1]);
        }
    }

    int ibase = bi * TILE;
    int jbase = bj * TILE;
    #pragma unroll
    for (int i = 0; i < 4; i++) {
        int ii = ibase + 4 * ty + i;
        int off = ii * (N_NODES - 1) - ((ii * (ii - 1)) >> 1) - ii - 1;
        #pragma unroll
        for (int jp = 0; jp < 2; jp++) {
            float2 s = make_float2(0.f, 0.f);
            #pragma unroll
            for (int g = 0; g < 4; g++) {
                float2 p = __half22float2(acc[g][i][jp]);
                s.x += p.x; s.y += p.y;
            }
            int j0 = jbase + 4 * tx + 2 * jp;
            if (j0     > ii) out[off + j0]     = sigmoid_fast(s.x + c0);
            if (j0 + 1 > ii) out[off + j0 + 1] = sigmoid_fast(s.y + c0);
        }
    }
}

// =====================================================================
// Launch
// =====================================================================
extern "C" void kernel_launch(void* const* d_in, const int* in_sizes, int n_in,
                              void* d_out, int out_size) {
    const float* clean_features = (const float*)d_in[0];
    const int*   selected_nodes = (const int*)  d_in[1];
    const float* noise          = (const float*)d_in[2];
    const float* gcn1_w         = (const float*)d_in[3];
    const float* gcn1_b         = (const float*)d_in[4];
    const float* gcn2_w         = (const float*)d_in[5];
    const float* gcn2_b         = (const float*)d_in[6];
    const float* gcn3_w         = (const float*)d_in[7];
    const float* gcn3_b         = (const float*)d_in[8];
    const float* ew1            = (const float*)d_in[9];
    const float* eb1            = (const float*)d_in[10];
    const float* ew2            = (const float*)d_in[11];
    const float* eb2            = (const float*)d_in[12];

    float* out = (float*)d_out;
    float* trig_out = out;                    // [2048, 256]
    float* edge_out = out + N_NODES * FDIM;   // [2096128]

    cudaFuncSetAttribute(merged_kernel,
                         cudaFuncAttributeMaxDynamicSharedMemorySize,
                         SMEM_BYTES);

    merged_kernel<<<129, 1024, SMEM_BYTES>>>(
        clean_features, selected_nodes,
        gcn1_w, gcn1_b, gcn2_w, gcn2_b, gcn3_w, gcn3_b,
        noise, ew1, trig_out);

    gemv_hab<<<128, 256>>>(ew1, eb1);

    edge_kernel<<<NTILES + NFIX, 256>>>(ew2, eb2, trig_out, edge_out);
}

// round 14
// speedup vs baseline: 1.0503x; 1.0503x over previous
#include <cuda_runtime.h>
#include <cuda_fp16.h>
#include <cstdint>

#define N_NODES 2048
#define FDIM 256
#define HID 64
#define TEMPLATE 10
#define RPB 8

// -------- scratch (static device globals; no allocation) --------
__device__ float g_h3[FDIM];
__device__ float g_ha[HID];                  // h3 @ ew1[:256] + eb1  (per k)
__device__ float g_hb[HID];                  // h3 @ ew1[256:]        (per k)
__device__ float g_paT[HID * N_NODES];       // [k][node] 0.1*noise@ew1a (cols 0-9 zero)
__device__ float g_pbT[HID * N_NODES];       // [k][node] 0.1*noise@ew1b (cols 0-9 zero)

__device__ __forceinline__ float sigmoid_fast(float x) {
    float t;
    asm("tanh.approx.f32 %0, %1;" : "=f"(t) : "f"(0.5f * x));
    return fmaf(0.5f, t, 0.5f);
}

// =====================================================================
// Merged kernel: block 0 = GCN (w2/w3 smem-staged, w1 via registers);
// blocks 1..255 = noise GEMM (0.1*noise @ ew1), 8 rows each.
// Dynamic smem 88.6KB -> 2 blocks/SM (64 warps, occ 100%).
// smem layout (floats):
//   gcn : w3s 0..16384 | w2s 16384..20480 | proto 20480 | red 20736 (1024)
//         h1 21760 | h2 21824 | h3s 21888  (total 22144)
//   noise: tst 0 ([256][12]=3072) | part 3072 ([8][8][129]=8256)
// =====================================================================
#define SMEM_FLOATS 22144
#define SMEM_BYTES  (SMEM_FLOATS * 4)
#define TSTRIDE 12    // 48B row: 16B-aligned for LDS.128
#define PSTRIDE 129   // padded part row: conflict-free strided reduce

extern __shared__ float sm[];

__global__ __launch_bounds__(1024) void merged_kernel(
        const float* __restrict__ cf,  const int* __restrict__ sel,
        const float* __restrict__ w1, const float* __restrict__ b1,
        const float* __restrict__ w2, const float* __restrict__ b2,
        const float* __restrict__ w3, const float* __restrict__ b3,
        const float* __restrict__ noise,
        const float* __restrict__ ew1,
        float* __restrict__ trig_out) {
    int t = threadIdx.x;  // 0..1023
    int b = blockIdx.x;

    if (b == 0) {
        // ================= GCN block =================
        float* w3s   = sm;
        float* w2s   = sm + 16384;
        float* proto = sm + 20480;
        float* red   = sm + 20736;   // 1024 floats
        float* h1    = sm + 21760;
        float* h2    = sm + 21824;
        float* h3s   = sm + 21888;

        int sidx[TEMPLATE];
        #pragma unroll
        for (int q = 0; q < TEMPLATE; q++) sidx[q] = sel[q];

        int o1 = t & 63, kq1 = t >> 6;   // 16 chunks

        // layer1 weights -> registers (16/thread, R6-proven)
        float wv1[16];
        #pragma unroll
        for (int kk = 0; kk < 16; kk++)
            wv1[kk] = w1[(size_t)(kq1 * 16 + kk) * HID + o1];

        // stream w2 + w3 to smem (coalesced float4)
        ((float4*)w2s)[t] = ((const float4*)w2)[t];
        #pragma unroll
        for (int i = 0; i < 4; i++) {
            int idx = t + i * 1024;
            ((float4*)w3s)[idx] = ((const float4*)w3)[idx];
        }

        if (t < FDIM) {
            float s = 0.f;
            #pragma unroll
            for (int q = 0; q < TEMPLATE; q++)
                s += cf[(size_t)sidx[q] * FDIM + t];
            proto[t] = s * (1.0f / TEMPLATE);
        }
        __syncthreads();

        // layer1: 256 -> 64 (16 chunks of 16 k, register weights)
        {
            const float* p = proto + kq1 * 16;
            float a0 = 0.f, a1 = 0.f, a2 = 0.f, a3 = 0.f;
            #pragma unroll
            for (int kk = 0; kk < 16; kk += 4) {
                a0 = fmaf(p[kk],     wv1[kk],     a0);
                a1 = fmaf(p[kk + 1], wv1[kk + 1], a1);
                a2 = fmaf(p[kk + 2], wv1[kk + 2], a2);
                a3 = fmaf(p[kk + 3], wv1[kk + 3], a3);
            }
            red[kq1 * 64 + o1] = (a0 + a1) + (a2 + a3);
        }
        __syncthreads();
        if (t < HID) {
            float s = b1[t];
            #pragma unroll
            for (int c = 0; c < 16; c++) s += red[c * 64 + t];
            h1[t] = fmaxf(s, 0.f);
        }
        __syncthreads();

        // layer2: 64 -> 64 (16 chunks of 4 k, smem weights)
        {
            int kb = kq1 * 4;
            float a0 = fmaf(h1[kb],   w2s[(kb)  *HID + o1], 0.f);
            float a1 = fmaf(h1[kb+1], w2s[(kb+1)*HID + o1], 0.f);
            a0 = fmaf(h1[kb+2], w2s[(kb+2)*HID + o1], a0);
            a1 = fmaf(h1[kb+3], w2s[(kb+3)*HID + o1], a1);
            red[kq1 * 64 + o1] = a0 + a1;
        }
        __syncthreads();
        if (t < HID) {
            float s = b2[t];
            #pragma unroll
            for (int c = 0; c < 16; c++) s += red[c * 64 + t];
            h2[t] = fmaxf(s, 0.f);
        }
        __syncthreads();

        // layer3: 64 -> 256 (4 chunks of 16 k, smem weights)
        {
            int o3 = t & 255, kh3 = t >> 8;
            int kb = kh3 * 16;
            float a0 = 0.f, a1 = 0.f, a2 = 0.f, a3 = 0.f;
            #pragma unroll
            for (int kk = 0; kk < 16; kk += 4) {
                a0 = fmaf(h2[kb+kk],   w3s[(kb+kk)  *FDIM + o3], a0);
                a1 = fmaf(h2[kb+kk+1], w3s[(kb+kk+1)*FDIM + o3], a1);
                a2 = fmaf(h2[kb+kk+2], w3s[(kb+kk+2)*FDIM + o3], a2);
                a3 = fmaf(h2[kb+kk+3], w3s[(kb+kk+3)*FDIM + o3], a3);
            }
            red[kh3 * 256 + o3] = (a0 + a1) + (a2 + a3);
        }
        __syncthreads();
        if (t < FDIM) {
            float a = red[t] + red[256 + t] + red[512 + t] + red[768 + t] + b3[t];
            float v = 1.0f / (1.0f + __expf(-a));
            h3s[t] = v;
            g_h3[t] = v;
            #pragma unroll
            for (int r = 0; r < TEMPLATE; r++)
                trig_out[(size_t)r * FDIM + t] = v;
        }
        // zero paT/pbT columns 0..9 (all 64 k rows)
        if (t < HID * TEMPLATE) {
            int k = t / TEMPLATE, node = t % TEMPLATE;
            g_paT[(size_t)k * N_NODES + node] = 0.f;
            g_pbT[(size_t)k * N_NODES + node] = 0.f;
        }
        return;
    }

    // ================= noise GEMM blocks (8 rows each) =================
    float* tst  = sm;                       // [256][TSTRIDE]
    float* part = sm + FDIM * TSTRIDE;      // [8][8][PSTRIDE]
    int r0 = TEMPLATE + (b - 1) * RPB;

    // prologue: load 0.1*noise (transposed into tst), write trig noise rows
    {
        int k = t & 255, g = t >> 8;        // g in 0..3 -> rows 2g, 2g+1
        #pragma unroll
        for (int rr2 = 0; rr2 < 2; rr2++) {
            int rr = 2 * g + rr2;
            int r = r0 + rr;
            if (r < N_NODES) {
                float v = 0.1f * noise[(size_t)(r - TEMPLATE) * FDIM + k];
                tst[k * TSTRIDE + rr] = v;
                trig_out[(size_t)r * FDIM + k] = v;
            } else {
                tst[k * TSTRIDE + rr] = 0.f;
            }
        }
    }
    __syncthreads();

    // GEMM: o = t&127 (half 0 -> pa col, half 1 -> pb col), c = t>>7
    // 8 k-chunks of 32; 8 row accumulators per thread.
    {
        int o = t & 127, c = t >> 7;
        int half = o >> 6, oc = o & 63;
        const float* w = ew1 + ((size_t)half * FDIM + c * 32) * HID + oc;
        const float* tb = tst + (c * 32) * TSTRIDE;

        float acc[RPB];
        #pragma unroll
        for (int rr = 0; rr < RPB; rr++) acc[rr] = 0.f;

        #pragma unroll 4
        for (int kk = 0; kk < 32; kk++) {
            float wu = w[(size_t)kk * HID];
            const float* row = tb + kk * TSTRIDE;
            float4 rA = *(const float4*)(row);       // rows 0..3 (bcast)
            float4 rB = *(const float4*)(row + 4);   // rows 4..7
            acc[0] = fmaf(rA.x, wu, acc[0]);
            acc[1] = fmaf(rA.y, wu, acc[1]);
            acc[2] = fmaf(rA.z, wu, acc[2]);
            acc[3] = fmaf(rA.w, wu, acc[3]);
            acc[4] = fmaf(rB.x, wu, acc[4]);
            acc[5] = fmaf(rB.y, wu, acc[5]);
            acc[6] = fmaf(rB.z, wu, acc[6]);
            acc[7] = fmaf(rB.w, wu, acc[7]);
        }
        #pragma unroll
        for (int rr = 0; rr < RPB; rr++)
            part[(c * RPB + rr) * PSTRIDE + o] = acc[rr];
    }
    __syncthreads();

    // reduce 8 chunks; TRANSPOSED store to g_paT/g_pbT[k][node]
    // 1024 outputs (8 rows x 128 cols), one per thread; lanes vary rr.
    {
        int rr = t & 7, oo = t >> 3;
        int r = r0 + rr;
        if (r < N_NODES) {
            float s = 0.f;
            #pragma unroll
            for (int cc = 0; cc < 8; cc++)
                s += part[(cc * RPB + rr) * PSTRIDE + oo];
            int hh = oo >> 6, occ = oo & 63;
            if (hh == 0) g_paT[(size_t)occ * N_NODES + r] = s;
            else         g_pbT[(size_t)occ * N_NODES + r] = s;
        }
    }
}

// =====================================================================
// gemv_hab: ha = h3 @ ew1[:256] + eb1 ; hb = h3 @ ew1[256:]
// =====================================================================
__global__ __launch_bounds__(256) void gemv_hab(
        const float* __restrict__ ew1, const float* __restrict__ eb1) {
    __shared__ float red[8];
    int b = blockIdx.x;            // 0..127
    int half = b >> 6, oc = b & 63;
    int t = threadIdx.x;           // 0..255

    float v = g_h3[t] * ew1[((size_t)(half * FDIM + t)) * HID + oc];
    #pragma unroll
    for (int off = 16; off > 0; off >>= 1)
        v += __shfl_xor_sync(0xffffffffu, v, off);
    if ((t & 31) == 0) red[t >> 5] = v;
    __syncthreads();
    if (t == 0) {
        float s = red[0] + red[1] + red[2] + red[3] +
                  red[4] + red[5] + red[6] + red[7];
        if (half == 0) g_ha[oc] = s + eb1[oc];
        else           g_hb[oc] = s;
    }
}

// =====================================================================
// Edge kernel (fp16x2 math, exact R12): blocks 0..527 = tiles;
// blocks 528..543 = trig fixup. 256 threads, per-thread 4i x 4j.
// =====================================================================
#define TILE 64
#define HPAD 72                       // half-row stride
#define NT   (N_NODES / TILE)         // 32
#define NTILES (NT * (NT + 1) / 2)    // 528
#define NFIX 16

__global__ __launch_bounds__(256) void edge_kernel(const float* __restrict__ ew2,
                                                   const float* __restrict__ eb2,
                                                   float* __restrict__ trig_out,
                                                   float* __restrict__ out) {
    int m = blockIdx.x;
    int tid = threadIdx.x;

    if (m >= NTILES) {
        // -------- trig fixup: trig[10:][:] += h3 (float4) --------
        int f = m - NTILES;                                  // 0..15
        const int total4 = (N_NODES - TEMPLATE) * FDIM / 4;  // 130432
        const int per = (total4 + NFIX - 1) / NFIX;
        int s = f * per;
        int e = s + per; if (e > total4) e = total4;
        float4* base = (float4*)(trig_out + (size_t)TEMPLATE * FDIM);
        for (int i = s + tid; i < e; i += 256) {
            int c4 = i & 63;
            float4 h = __ldg((const float4*)&g_h3[c4 * 4]);
            float4 v = base[i];
            v.x += h.x; v.y += h.y; v.z += h.z; v.w += h.w;
            base[i] = v;
        }
        return;
    }

    // decode (bi, bj) with bj >= bi from m
    int bi = (int)(32.5f - sqrtf(32.5f * 32.5f - 2.0f * (float)m));
    while (bi * NT - ((bi * (bi - 1)) >> 1) > m) bi--;
    while ((bi + 1) * NT - (((bi + 1) * bi) >> 1) <= m) bi++;
    int bj = bi + (m - (bi * NT - ((bi * (bi - 1)) >> 1)));

    __shared__ __half pah[HID][HPAD];     // [k][i], +ha folded
    __shared__ __half pbh[HID][HPAD];     // [k][j], +hb folded
    __shared__ __half2 w2h[HID];          // (w,w) pairs

    // tile load: g_paT/g_pbT are [k][node] float; convert to half
    {
        const float* paG = g_paT + (size_t)bi * TILE;
        const float* pbG = g_pbT + (size_t)bj * TILE;
        #pragma unroll
        for (int it = 0; it < 4; it++) {
            int idx = tid + it * 256;     // 1024 slots: k = idx>>4, c4
            int k = idx >> 4;
            int c4 = (idx & 15) << 2;
            float hav = __ldg(&g_ha[k]);
            float hbv = __ldg(&g_hb[k]);
            float4 va = *(const float4*)(paG + (size_t)k * N_NODES + c4);
            __half2 pa01 = __floats2half2_rn(va.x + hav, va.y + hav);
            __half2 pa23 = __floats2half2_rn(va.z + hav, va.w + hav);
            *(__half2*)&pah[k][c4]     = pa01;
            *(__half2*)&pah[k][c4 + 2] = pa23;
            float4 vb = *(const float4*)(pbG + (size_t)k * N_NODES + c4);
            __half2 pb01 = __floats2half2_rn(vb.x + hbv, vb.y + hbv);
            __half2 pb23 = __floats2half2_rn(vb.z + hbv, vb.w + hbv);
            *(__half2*)&pbh[k][c4]     = pb01;
            *(__half2*)&pbh[k][c4 + 2] = pb23;
        }
        if (tid < HID) w2h[tid] = __float2half2_rn(ew2[tid]);
    }
    float c0 = eb2[0];
    __syncthreads();

    int tx = tid & 15;   // j-group: j = 4*tx + (0..3)
    int ty = tid >> 4;   // i-group: i = 4*ty + (0..3)

    const __half2 zero2 = __float2half2_rn(0.0f);
    // acc[group][i][jp]: 4 interleaved 16-term fp16 partial sums
    __half2 acc[4][4][2];
    #pragma unroll
    for (int g = 0; g < 4; g++)
        #pragma unroll
        for (int i = 0; i < 4; i++) {
            acc[g][i][0] = zero2;
            acc[g][i][1] = zero2;
        }

    #pragma unroll 4
    for (int k = 0; k < HID; k++) {
        int g = k & 3;
        __half2 wk = w2h[k];
        __half2 a01 = *(const __half2*)&pah[k][4 * ty];
        __half2 a23 = *(const __half2*)&pah[k][4 * ty + 2];
        __half2 b01 = *(const __half2*)&pbh[k][4 * tx];
        __half2 b23 = *(const __half2*)&pbh[k][4 * tx + 2];
        __half2 ai[4];
        ai[0] = __lows2half2(a01, a01);
        ai[1] = __highs2half2(a01, a01);
        ai[2] = __lows2half2(a23, a23);
        ai[3] = __highs2half2(a23, a23);
        #pragma unroll
        for (int i = 0; i < 4; i++) {
            __half2 s0 = __hmax2(__hadd2(ai[i], b01), zero2);
            __half2 s1 = __hmax2(__hadd2(ai[i], b23), zero2);
            acc[g][i][0] = __hfma2(s0, wk, acc[g][i][0]);
            acc[g][i][1] = __hfma2(s1, wk, acc[g][i][1]);
        }
    }

    int ibase = bi * TILE;
    int jbase = bj * TILE;
    #pragma unroll
    for (int i = 0; i < 4; i++) {
        int ii = ibase + 4 * ty + i;
        int off = ii * (N_NODES - 1) - ((ii * (ii - 1)) >> 1) - ii - 1;
        #pragma unroll
        for (int jp = 0; jp < 2; jp++) {
            float2 s = make_float2(0.f, 0.f);
            #pragma unroll
            for (int g = 0; g < 4; g++) {
                float2 p = __half22float2(acc[g][i][jp]);
                s.x += p.x; s.y += p.y;
            }
            int j0 = jbase + 4 * tx + 2 * jp;
            if (j0     > ii) out[off + j0]     = sigmoid_fast(s.x + c0);
            if (j0 + 1 > ii) out[off + j0 + 1] = sigmoid_fast(s.y + c0);
        }
    }
}

// =====================================================================
// Launch
// =====================================================================
extern "C" void kernel_launch(void* const* d_in, const int* in_sizes, int n_in,
                              void* d_out, int out_size) {
    const float* clean_features = (const float*)d_in[0];
    const int*   selected_nodes = (const int*)  d_in[1];
    const float* noise          = (const float*)d_in[2];
    const float* gcn1_w         = (const float*)d_in[3];
    const float* gcn1_b         = (const float*)d_in[4];
    const float* gcn2_w         = (const float*)d_in[5];
    const float* gcn2_b         = (const float*)d_in[6];
    const float* gcn3_w         = (const float*)d_in[7];
    const float* gcn3_b         = (const float*)d_in[8];
    const float* ew1            = (const float*)d_in[9];
    const float* eb1            = (const float*)d_in[10];
    const float* ew2            = (const float*)d_in[11];
    const float* eb2            = (const float*)d_in[12];

    float* out = (float*)d_out;
    float* trig_out = out;                    // [2048, 256]
    float* edge_out = out + N_NODES * FDIM;   // [2096128]

    cudaFuncSetAttribute(merged_kernel,
                         cudaFuncAttributeMaxDynamicSharedMemorySize,
                         SMEM_BYTES);

    // 1 gcn block + 255 noise blocks (255*8 = 2040 >= 2038 rows); 88.6KB
    // dynamic smem -> 2 blocks/SM, single wave.
    merged_kernel<<<256, 1024, SMEM_BYTES>>>(
        clean_features, selected_nodes,
        gcn1_w, gcn1_b, gcn2_w, gcn2_b, gcn3_w, gcn3_b,
        noise, ew1, trig_out);

    gemv_hab<<<128, 256>>>(ew1, eb1);

    edge_kernel<<<NTILES + NFIX, 256>>>(ew2, eb2, trig_out, edge_out);
}

// round 16
// speedup vs baseline: 1.0656x; 1.0146x over previous
#include <cuda_runtime.h>
#include <cuda_fp16.h>
#include <cstdint>

#define N_NODES 2048
#define FDIM 256
#define HID 64
#define TEMPLATE 10
#define RPB 8

// -------- scratch (static device globals; no allocation) --------
__device__ float g_h3[FDIM];
__device__ float g_ha[HID];                  // h3 @ ew1[:256] + eb1  (per k)
__device__ float g_hb[HID];                  // h3 @ ew1[256:]        (per k)
__device__ float g_paT[HID * N_NODES];       // [k][node] 0.1*noise@ew1a (cols 0-9 zero)
__device__ float g_pbT[HID * N_NODES];       // [k][node] 0.1*noise@ew1b (cols 0-9 zero)

__device__ __forceinline__ float sigmoid_fast(float x) {
    float t;
    asm("tanh.approx.f32 %0, %1;" : "=f"(t) : "f"(0.5f * x));
    return fmaf(0.5f, t, 0.5f);
}

// =====================================================================
// Merged kernel: block 0 = GCN (w2/w3 smem-staged, w1 via registers);
// blocks 1..255 = noise GEMM (0.1*noise @ ew1), 8 rows each.
// __launch_bounds__(1024, 2): cap regs at 32 so TWO 1024-thread blocks
// fit per SM (was register-capped at 1 with regs=46).
// smem layout (floats):
//   gcn : w3s 0..16384 | w2s 16384..20480 | proto 20480 | red 20736 (1024)
//         h1 21760 | h2 21824 | h3s 21888  (total 22144)
//   noise: tst 0 ([256][12]=3072) | part 3072 ([8][8][129]=8256)
// =====================================================================
#define SMEM_FLOATS 22144
#define SMEM_BYTES  (SMEM_FLOATS * 4)
#define TSTRIDE 12    // 48B row: 16B-aligned for LDS.128
#define PSTRIDE 129   // padded part row: conflict-free strided reduce

extern __shared__ float sm[];

__global__ __launch_bounds__(1024, 2) void merged_kernel(
        const float* __restrict__ cf,  const int* __restrict__ sel,
        const float* __restrict__ w1, const float* __restrict__ b1,
        const float* __restrict__ w2, const float* __restrict__ b2,
        const float* __restrict__ w3, const float* __restrict__ b3,
        const float* __restrict__ noise,
        const float* __restrict__ ew1,
        float* __restrict__ trig_out) {
    int t = threadIdx.x;  // 0..1023
    int b = blockIdx.x;

    if (b == 0) {
        // ================= GCN block =================
        float* w3s   = sm;
        float* w2s   = sm + 16384;
        float* proto = sm + 20480;
        float* red   = sm + 20736;   // 1024 floats
        float* h1    = sm + 21760;
        float* h2    = sm + 21824;
        float* h3s   = sm + 21888;

        int sidx[TEMPLATE];
        #pragma unroll
        for (int q = 0; q < TEMPLATE; q++) sidx[q] = sel[q];

        int o1 = t & 63, kq1 = t >> 6;   // 16 chunks

        // layer1 weights -> registers (16/thread; may partially spill to
        // L1-resident local under the 32-reg cap -- acceptable, one block)
        float wv1[16];
        #pragma unroll
        for (int kk = 0; kk < 16; kk++)
            wv1[kk] = w1[(size_t)(kq1 * 16 + kk) * HID + o1];

        // stream w2 + w3 to smem (coalesced float4)
        ((float4*)w2s)[t] = ((const float4*)w2)[t];
        #pragma unroll
        for (int i = 0; i < 4; i++) {
            int idx = t + i * 1024;
            ((float4*)w3s)[idx] = ((const float4*)w3)[idx];
        }

        if (t < FDIM) {
            float s = 0.f;
            #pragma unroll
            for (int q = 0; q < TEMPLATE; q++)
                s += cf[(size_t)sidx[q] * FDIM + t];
            proto[t] = s * (1.0f / TEMPLATE);
        }
        __syncthreads();

        // layer1: 256 -> 64 (16 chunks of 16 k, register weights)
        {
            const float* p = proto + kq1 * 16;
            float a0 = 0.f, a1 = 0.f, a2 = 0.f, a3 = 0.f;
            #pragma unroll
            for (int kk = 0; kk < 16; kk += 4) {
                a0 = fmaf(p[kk],     wv1[kk],     a0);
                a1 = fmaf(p[kk + 1], wv1[kk + 1], a1);
                a2 = fmaf(p[kk + 2], wv1[kk + 2], a2);
                a3 = fmaf(p[kk + 3], wv1[kk + 3], a3);
            }
            red[kq1 * 64 + o1] = (a0 + a1) + (a2 + a3);
        }
        __syncthreads();
        if (t < HID) {
            float s = b1[t];
            #pragma unroll
            for (int c = 0; c < 16; c++) s += red[c * 64 + t];
            h1[t] = fmaxf(s, 0.f);
        }
        __syncthreads();

        // layer2: 64 -> 64 (16 chunks of 4 k, smem weights)
        {
            int kb = kq1 * 4;
            float a0 = fmaf(h1[kb],   w2s[(kb)  *HID + o1], 0.f);
            float a1 = fmaf(h1[kb+1], w2s[(kb+1)*HID + o1], 0.f);
            a0 = fmaf(h1[kb+2], w2s[(kb+2)*HID + o1], a0);
            a1 = fmaf(h1[kb+3], w2s[(kb+3)*HID + o1], a1);
            red[kq1 * 64 + o1] = a0 + a1;
        }
        __syncthreads();
        if (t < HID) {
            float s = b2[t];
            #pragma unroll
            for (int c = 0; c < 16; c++) s += red[c * 64 + t];
            h2[t] = fmaxf(s, 0.f);
        }
        __syncthreads();

        // layer3: 64 -> 256 (4 chunks of 16 k, smem weights)
        {
            int o3 = t & 255, kh3 = t >> 8;
            int kb = kh3 * 16;
            float a0 = 0.f, a1 = 0.f, a2 = 0.f, a3 = 0.f;
            #pragma unroll
            for (int kk = 0; kk < 16; kk += 4) {
                a0 = fmaf(h2[kb+kk],   w3s[(kb+kk)  *FDIM + o3], a0);
                a1 = fmaf(h2[kb+kk+1], w3s[(kb+kk+1)*FDIM + o3], a1);
                a2 = fmaf(h2[kb+kk+2], w3s[(kb+kk+2)*FDIM + o3], a2);
                a3 = fmaf(h2[kb+kk+3], w3s[(kb+kk+3)*FDIM + o3], a3);
            }
            red[kh3 * 256 + o3] = (a0 + a1) + (a2 + a3);
        }
        __syncthreads();
        if (t < FDIM) {
            float a = red[t] + red[256 + t] + red[512 + t] + red[768 + t] + b3[t];
            float v = 1.0f / (1.0f + __expf(-a));
            h3s[t] = v;
            g_h3[t] = v;
            #pragma unroll
            for (int r = 0; r < TEMPLATE; r++)
                trig_out[(size_t)r * FDIM + t] = v;
        }
        // zero paT/pbT columns 0..9 (all 64 k rows)
        if (t < HID * TEMPLATE) {
            int k = t / TEMPLATE, node = t % TEMPLATE;
            g_paT[(size_t)k * N_NODES + node] = 0.f;
            g_pbT[(size_t)k * N_NODES + node] = 0.f;
        }
        return;
    }

    // ================= noise GEMM blocks (8 rows each) =================
    float* tst  = sm;                       // [256][TSTRIDE]
    float* part = sm + FDIM * TSTRIDE;      // [8][8][PSTRIDE]
    int r0 = TEMPLATE + (b - 1) * RPB;

    // prologue: load 0.1*noise (transposed into tst), write trig noise rows
    {
        int k = t & 255, g = t >> 8;        // g in 0..3 -> rows 2g, 2g+1
        #pragma unroll
        for (int rr2 = 0; rr2 < 2; rr2++) {
            int rr = 2 * g + rr2;
            int r = r0 + rr;
            if (r < N_NODES) {
                float v = 0.1f * noise[(size_t)(r - TEMPLATE) * FDIM + k];
                tst[k * TSTRIDE + rr] = v;
                trig_out[(size_t)r * FDIM + k] = v;
            } else {
                tst[k * TSTRIDE + rr] = 0.f;
            }
        }
    }
    __syncthreads();

    // GEMM: o = t&127 (half 0 -> pa col, half 1 -> pb col), c = t>>7
    // 8 k-chunks of 32; 8 row accumulators per thread.
    {
        int o = t & 127, c = t >> 7;
        int half = o >> 6, oc = o & 63;
        const float* w = ew1 + ((size_t)half * FDIM + c * 32) * HID + oc;
        const float* tb = tst + (c * 32) * TSTRIDE;

        float acc[RPB];
        #pragma unroll
        for (int rr = 0; rr < RPB; rr++) acc[rr] = 0.f;

        #pragma unroll 4
        for (int kk = 0; kk < 32; kk++) {
            float wu = w[(size_t)kk * HID];
            const float* row = tb + kk * TSTRIDE;
            float4 rA = *(const float4*)(row);       // rows 0..3 (bcast)
            float4 rB = *(const float4*)(row + 4);   // rows 4..7
            acc[0] = fmaf(rA.x, wu, acc[0]);
            acc[1] = fmaf(rA.y, wu, acc[1]);
            acc[2] = fmaf(rA.z, wu, acc[2]);
            acc[3] = fmaf(rA.w, wu, acc[3]);
            acc[4] = fmaf(rB.x, wu, acc[4]);
            acc[5] = fmaf(rB.y, wu, acc[5]);
            acc[6] = fmaf(rB.z, wu, acc[6]);
            acc[7] = fmaf(rB.w, wu, acc[7]);
        }
        #pragma unroll
        for (int rr = 0; rr < RPB; rr++)
            part[(c * RPB + rr) * PSTRIDE + o] = acc[rr];
    }
    __syncthreads();

    // reduce 8 chunks; TRANSPOSED store to g_paT/g_pbT[k][node]
    // 1024 outputs (8 rows x 128 cols), one per thread; lanes vary rr.
    {
        int rr = t & 7, oo = t >> 3;
        int r = r0 + rr;
        if (r < N_NODES) {
            float s = 0.f;
            #pragma unroll
            for (int cc = 0; cc < 8; cc++)
                s += part[(cc * RPB + rr) * PSTRIDE + oo];
            int hh = oo >> 6, occ = oo & 63;
            if (hh == 0) g_paT[(size_t)occ * N_NODES + r] = s;
            else         g_pbT[(size_t)occ * N_NODES + r] = s;
        }
    }
}

// =====================================================================
// gemv_hab: ha = h3 @ ew1[:256] + eb1 ; hb = h3 @ ew1[256:]
// =====================================================================
__global__ __launch_bounds__(256) void gemv_hab(
        const float* __restrict__ ew1, const float* __restrict__ eb1) {
    __shared__ float red[8];
    int b = blockIdx.x;            // 0..127
    int half = b >> 6, oc = b & 63;
    int t = threadIdx.x;           // 0..255

    float v = g_h3[t] * ew1[((size_t)(half * FDIM + t)) * HID + oc];
    #pragma unroll
    for (int off = 16; off > 0; off >>= 1)
        v += __shfl_xor_sync(0xffffffffu, v, off);
    if ((t & 31) == 0) red[t >> 5] = v;
    __syncthreads();
    if (t == 0) {
        float s = red[0] + red[1] + red[2] + red[3] +
                  red[4] + red[5] + red[6] + red[7];
        if (half == 0) g_ha[oc] = s + eb1[oc];
        else           g_hb[oc] = s;
    }
}

// =====================================================================
// Edge kernel (fp16x2 math, exact R12): blocks 0..527 = tiles;
// blocks 528..543 = trig fixup. 256 threads, per-thread 4i x 4j.
// =====================================================================
#define TILE 64
#define HPAD 72                       // half-row stride
#define NT   (N_NODES / TILE)         // 32
#define NTILES (NT * (NT + 1) / 2)    // 528
#define NFIX 16

__global__ __launch_bounds__(256) void edge_kernel(const float* __restrict__ ew2,
                                                   const float* __restrict__ eb2,
                                                   float* __restrict__ trig_out,
                                                   float* __restrict__ out) {
    int m = blockIdx.x;
    int tid = threadIdx.x;

    if (m >= NTILES) {
        // -------- trig fixup: trig[10:][:] += h3 (float4) --------
        int f = m - NTILES;                                  // 0..15
        const int total4 = (N_NODES - TEMPLATE) * FDIM / 4;  // 130432
        const int per = (total4 + NFIX - 1) / NFIX;
        int s = f * per;
        int e = s + per; if (e > total4) e = total4;
        float4* base = (float4*)(trig_out + (size_t)TEMPLATE * FDIM);
        for (int i = s + tid; i < e; i += 256) {
            int c4 = i & 63;
            float4 h = __ldg((const float4*)&g_h3[c4 * 4]);
            float4 v = base[i];
            v.x += h.x; v.y += h.y; v.z += h.z; v.w += h.w;
            base[i] = v;
        }
        return;
    }

    // decode (bi, bj) with bj >= bi from m
    int bi = (int)(32.5f - sqrtf(32.5f * 32.5f - 2.0f * (float)m));
    while (bi * NT - ((bi * (bi - 1)) >> 1) > m) bi--;
    while ((bi + 1) * NT - (((bi + 1) * bi) >> 1) <= m) bi++;
    int bj = bi + (m - (bi * NT - ((bi * (bi - 1)) >> 1)));

    __shared__ __half pah[HID][HPAD];     // [k][i], +ha folded
    __shared__ __half pbh[HID][HPAD];     // [k][j], +hb folded
    __shared__ __half2 w2h[HID];          // (w,w) pairs

    // tile load: g_paT/g_pbT are [k][node] float; convert to half
    {
        const float* paG = g_paT + (size_t)bi * TILE;
        const float* pbG = g_pbT + (size_t)bj * TILE;
        #pragma unroll
        for (int it = 0; it < 4; it++) {
            int idx = tid + it * 256;     // 1024 slots: k = idx>>4, c4
            int k = idx >> 4;
            int c4 = (idx & 15) << 2;
            float hav = __ldg(&g_ha[k]);
            float hbv = __ldg(&g_hb[k]);
            float4 va = *(const float4*)(paG + (size_t)k * N_NODES + c4);
            __half2 pa01 = __floats2half2_rn(va.x + hav, va.y + hav);
            __half2 pa23 = __floats2half2_rn(va.z + hav, va.w + hav);
            *(__half2*)&pah[k][c4]     = pa01;
            *(__half2*)&pah[k][c4 + 2] = pa23;
            float4 vb = *(const float4*)(pbG + (size_t)k * N_NODES + c4);
            __half2 pb01 = __floats2half2_rn(vb.x + hbv, vb.y + hbv);
            __half2 pb23 = __floats2half2_rn(vb.z + hbv, vb.w + hbv);
            *(__half2*)&pbh[k][c4]     = pb01;
            *(__half2*)&pbh[k][c4 + 2] = pb23;
        }
        if (tid < HID) w2h[tid] = __float2half2_rn(ew2[tid]);
    }
    float c0 = eb2[0];
    __syncthreads();

    int tx = tid & 15;   // j-group: j = 4*tx + (0..3)
    int ty = tid >> 4;   // i-group: i = 4*ty + (0..3)

    const __half2 zero2 = __float2half2_rn(0.0f);
    // acc[group][i][jp]: 4 interleaved 16-term fp16 partial sums
    __half2 acc[4][4][2];
    #pragma unroll
    for (int g = 0; g < 4; g++)
        #pragma unroll
        for (int i = 0; i < 4; i++) {
            acc[g][i][0] = zero2;
            acc[g][i][1] = zero2;
        }

    #pragma unroll 4
    for (int k = 0; k < HID; k++) {
        int g = k & 3;
        __half2 wk = w2h[k];
        __half2 a01 = *(const __half2*)&pah[k][4 * ty];
        __half2 a23 = *(const __half2*)&pah[k][4 * ty + 2];
        __half2 b01 = *(const __half2*)&pbh[k][4 * tx];
        __half2 b23 = *(const __half2*)&pbh[k][4 * tx + 2];
        __half2 ai[4];
        ai[0] = __lows2half2(a01, a01);
        ai[1] = __highs2half2(a01, a01);
        ai[2] = __lows2half2(a23, a23);
        ai[3] = __highs2half2(a23, a23);
        #pragma unroll
        for (int i = 0; i < 4; i++) {
            __half2 s0 = __hmax2(__hadd2(ai[i], b01), zero2);
            __half2 s1 = __hmax2(__hadd2(ai[i], b23), zero2);
            acc[g][i][0] = __hfma2(s0, wk, acc[g][i][0]);
            acc[g][i][1] = __hfma2(s1, wk, acc[g][i][1]);
        }
    }

    int ibase = bi * TILE;
    int jbase = bj * TILE;
    #pragma unroll
    for (int i = 0; i < 4; i++) {
        int ii = ibase + 4 * ty + i;
        int off = ii * (N_NODES - 1) - ((ii * (ii - 1)) >> 1) - ii - 1;
        #pragma unroll
        for (int jp = 0; jp < 2; jp++) {
            float2 s = make_float2(0.f, 0.f);
            #pragma unroll
            for (int g = 0; g < 4; g++) {
                float2 p = __half22float2(acc[g][i][jp]);
                s.x += p.x; s.y += p.y;
            }
            int j0 = jbase + 4 * tx + 2 * jp;
            if (j0     > ii) out[off + j0]     = sigmoid_fast(s.x + c0);
            if (j0 + 1 > ii) out[off + j0 + 1] = sigmoid_fast(s.y + c0);
        }
    }
}

// =====================================================================
// Launch
// =====================================================================
extern "C" void kernel_launch(void* const* d_in, const int* in_sizes, int n_in,
                              void* d_out, int out_size) {
    const float* clean_features = (const float*)d_in[0];
    const int*   selected_nodes = (const int*)  d_in[1];
    const float* noise          = (const float*)d_in[2];
    const float* gcn1_w         = (const float*)d_in[3];
    const float* gcn1_b         = (const float*)d_in[4];
    const float* gcn2_w         = (const float*)d_in[5];
    const float* gcn2_b         = (const float*)d_in[6];
    const float* gcn3_w         = (const float*)d_in[7];
    const float* gcn3_b         = (const float*)d_in[8];
    const float* ew1            = (const float*)d_in[9];
    const float* eb1            = (const float*)d_in[10];
    const float* ew2            = (const float*)d_in[11];
    const float* eb2            = (const float*)d_in[12];

    float* out = (float*)d_out;
    float* trig_out = out;                    // [2048, 256]
    float* edge_out = out + N_NODES * FDIM;   // [2096128]

    cudaFuncSetAttribute(merged_kernel,
                         cudaFuncAttributeMaxDynamicSharedMemorySize,
                         SMEM_BYTES);

    // 1 gcn block + 255 noise blocks; 88.6KB smem + 32-reg cap
    // -> 2 blocks/SM (occ 100%), ~1 wave of 128 SM-pairs.
    merged_kernel<<<256, 1024, SMEM_BYTES>>>(
        clean_features, selected_nodes,
        gcn1_w, gcn1_b, gcn2_w, gcn2_b, gcn3_w, gcn3_b,
        noise, ew1, trig_out);

    gemv_hab<<<128, 256>>>(ew1, eb1);

    edge_kernel<<<NTILES + NFIX, 256>>>(ew2, eb2, trig_out, edge_out);
}

// round 17
// speedup vs baseline: 1.1327x; 1.0631x over previous
#include <cuda_runtime.h>
#include <cuda_fp16.h>
#include <cstdint>

#define N_NODES 2048
#define FDIM 256
#define HID 64
#define TEMPLATE 10
#define RPB 8

// -------- scratch (static device globals; no allocation) --------
__device__ float g_h3[FDIM];
__device__ float g_ha[HID];                  // h3 @ ew1[:256] + eb1  (per k)
__device__ float g_hb[HID];                  // h3 @ ew1[256:]        (per k)
__device__ float g_paT[HID * N_NODES];       // [k][node] 0.1*noise@ew1a (cols 0-9 zero)
__device__ float g_pbT[HID * N_NODES];       // [k][node] 0.1*noise@ew1b (cols 0-9 zero)

__device__ __forceinline__ float sigmoid_fast(float x) {
    float t;
    asm("tanh.approx.f32 %0, %1;" : "=f"(t) : "f"(0.5f * x));
    return fmaf(0.5f, t, 0.5f);
}

// =====================================================================
// Merged kernel: block 0 = GCN + ha/hb GEMV (hidden behind noise side);
// blocks 1..255 = noise GEMM (0.1*noise @ ew1), 8 rows each.
// __launch_bounds__(1024, 2): 32-reg cap -> 2 blocks/SM.
// smem layout (floats):
//   gcn : w3s 0..16384 | w2s 16384..20480 | proto 20480 | red 20736 (1024)
//         h1 21760 | h2 21824 | h3s 21888  (total 22144)
//   noise: tst 0 ([256][12]=3072) | part 3072 ([8][8][129]=8256)
// =====================================================================
#define SMEM_FLOATS 22144
#define SMEM_BYTES  (SMEM_FLOATS * 4)
#define TSTRIDE 12    // 48B row: 16B-aligned for LDS.128
#define PSTRIDE 129   // padded part row: conflict-free strided reduce

extern __shared__ float sm[];

__global__ __launch_bounds__(1024, 2) void merged_kernel(
        const float* __restrict__ cf,  const int* __restrict__ sel,
        const float* __restrict__ w1, const float* __restrict__ b1,
        const float* __restrict__ w2, const float* __restrict__ b2,
        const float* __restrict__ w3, const float* __restrict__ b3,
        const float* __restrict__ noise,
        const float* __restrict__ ew1,
        const float* __restrict__ eb1,
        float* __restrict__ trig_out) {
    int t = threadIdx.x;  // 0..1023
    int b = blockIdx.x;

    if (b == 0) {
        // ================= GCN block =================
        float* w3s   = sm;
        float* w2s   = sm + 16384;
        float* proto = sm + 20480;
        float* red   = sm + 20736;   // 1024 floats
        float* h1    = sm + 21760;
        float* h2    = sm + 21824;
        float* h3s   = sm + 21888;

        int sidx[TEMPLATE];
        #pragma unroll
        for (int q = 0; q < TEMPLATE; q++) sidx[q] = sel[q];

        int o1 = t & 63, kq1 = t >> 6;   // 16 chunks

        // layer1 weights -> registers (16/thread; spills under the 32-reg
        // cap go to L1-resident local -- acceptable, single block)
        float wv1[16];
        #pragma unroll
        for (int kk = 0; kk < 16; kk++)
            wv1[kk] = w1[(size_t)(kq1 * 16 + kk) * HID + o1];

        // stream w2 + w3 to smem (coalesced float4)
        ((float4*)w2s)[t] = ((const float4*)w2)[t];
        #pragma unroll
        for (int i = 0; i < 4; i++) {
            int idx = t + i * 1024;
            ((float4*)w3s)[idx] = ((const float4*)w3)[idx];
        }

        if (t < FDIM) {
            float s = 0.f;
            #pragma unroll
            for (int q = 0; q < TEMPLATE; q++)
                s += cf[(size_t)sidx[q] * FDIM + t];
            proto[t] = s * (1.0f / TEMPLATE);
        }
        __syncthreads();

        // layer1: 256 -> 64 (16 chunks of 16 k, register weights)
        {
            const float* p = proto + kq1 * 16;
            float a0 = 0.f, a1 = 0.f, a2 = 0.f, a3 = 0.f;
            #pragma unroll
            for (int kk = 0; kk < 16; kk += 4) {
                a0 = fmaf(p[kk],     wv1[kk],     a0);
                a1 = fmaf(p[kk + 1], wv1[kk + 1], a1);
                a2 = fmaf(p[kk + 2], wv1[kk + 2], a2);
                a3 = fmaf(p[kk + 3], wv1[kk + 3], a3);
            }
            red[kq1 * 64 + o1] = (a0 + a1) + (a2 + a3);
        }
        __syncthreads();
        if (t < HID) {
            float s = b1[t];
            #pragma unroll
            for (int c = 0; c < 16; c++) s += red[c * 64 + t];
            h1[t] = fmaxf(s, 0.f);
        }
        __syncthreads();

        // layer2: 64 -> 64 (16 chunks of 4 k, smem weights)
        {
            int kb = kq1 * 4;
            float a0 = fmaf(h1[kb],   w2s[(kb)  *HID + o1], 0.f);
            float a1 = fmaf(h1[kb+1], w2s[(kb+1)*HID + o1], 0.f);
            a0 = fmaf(h1[kb+2], w2s[(kb+2)*HID + o1], a0);
            a1 = fmaf(h1[kb+3], w2s[(kb+3)*HID + o1], a1);
            red[kq1 * 64 + o1] = a0 + a1;
        }
        __syncthreads();
        if (t < HID) {
            float s = b2[t];
            #pragma unroll
            for (int c = 0; c < 16; c++) s += red[c * 64 + t];
            h2[t] = fmaxf(s, 0.f);
        }
        __syncthreads();

        // layer3: 64 -> 256 (4 chunks of 16 k, smem weights)
        {
            int o3 = t & 255, kh3 = t >> 8;
            int kb = kh3 * 16;
            float a0 = 0.f, a1 = 0.f, a2 = 0.f, a3 = 0.f;
            #pragma unroll
            for (int kk = 0; kk < 16; kk += 4) {
                a0 = fmaf(h2[kb+kk],   w3s[(kb+kk)  *FDIM + o3], a0);
                a1 = fmaf(h2[kb+kk+1], w3s[(kb+kk+1)*FDIM + o3], a1);
                a2 = fmaf(h2[kb+kk+2], w3s[(kb+kk+2)*FDIM + o3], a2);
                a3 = fmaf(h2[kb+kk+3], w3s[(kb+kk+3)*FDIM + o3], a3);
            }
            red[kh3 * 256 + o3] = (a0 + a1) + (a2 + a3);
        }
        __syncthreads();
        if (t < FDIM) {
            float a = red[t] + red[256 + t] + red[512 + t] + red[768 + t] + b3[t];
            float v = 1.0f / (1.0f + __expf(-a));
            h3s[t] = v;
            g_h3[t] = v;
            #pragma unroll
            for (int r = 0; r < TEMPLATE; r++)
                trig_out[(size_t)r * FDIM + t] = v;
        }
        // zero paT/pbT columns 0..9 (all 64 k rows)
        if (t < HID * TEMPLATE) {
            int k = t / TEMPLATE, node = t % TEMPLATE;
            g_paT[(size_t)k * N_NODES + node] = 0.f;
            g_pbT[(size_t)k * N_NODES + node] = 0.f;
        }
        __syncthreads();

        // ha = h3 @ ew1[:256] + eb1 ; hb = h3 @ ew1[256:]
        // (128KB ew1 read on this one SM, hidden behind the ~12.8us
        //  noise-GEMM tail running on the other SMs)
        {
            int o2 = t & 127, c2 = t >> 7;          // 8 chunks x 32 k
            int half = o2 >> 6, oc = o2 & 63;
            const float* w = ew1 + ((size_t)half * FDIM + c2 * 32) * HID + oc;
            const float* p = h3s + c2 * 32;
            float a0 = 0.f, a1 = 0.f;
            #pragma unroll
            for (int kk = 0; kk < 32; kk += 2) {
                a0 = fmaf(p[kk],     w[(size_t)(kk)     * HID], a0);
                a1 = fmaf(p[kk + 1], w[(size_t)(kk + 1) * HID], a1);
            }
            red[c2 * 128 + o2] = a0 + a1;
        }
        __syncthreads();
        if (t < 128) {
            int half = t >> 6, oc = t & 63;
            float s = 0.f;
            #pragma unroll
            for (int c = 0; c < 8; c++) s += red[c * 128 + t];
            if (half == 0) g_ha[oc] = s + eb1[oc];
            else           g_hb[oc] = s;
        }
        return;
    }

    // ================= noise GEMM blocks (8 rows each) =================
    float* tst  = sm;                       // [256][TSTRIDE]
    float* part = sm + FDIM * TSTRIDE;      // [8][8][PSTRIDE]
    int r0 = TEMPLATE + (b - 1) * RPB;

    // prologue: load 0.1*noise (transposed into tst), write trig noise rows
    {
        int k = t & 255, g = t >> 8;        // g in 0..3 -> rows 2g, 2g+1
        #pragma unroll
        for (int rr2 = 0; rr2 < 2; rr2++) {
            int rr = 2 * g + rr2;
            int r = r0 + rr;
            if (r < N_NODES) {
                float v = 0.1f * noise[(size_t)(r - TEMPLATE) * FDIM + k];
                tst[k * TSTRIDE + rr] = v;
                trig_out[(size_t)r * FDIM + k] = v;
            } else {
                tst[k * TSTRIDE + rr] = 0.f;
            }
        }
    }
    __syncthreads();

    // GEMM: o = t&127 (half 0 -> pa col, half 1 -> pb col), c = t>>7
    // 8 k-chunks of 32; 8 row accumulators per thread.
    {
        int o = t & 127, c = t >> 7;
        int half = o >> 6, oc = o & 63;
        const float* w = ew1 + ((size_t)half * FDIM + c * 32) * HID + oc;
        const float* tb = tst + (c * 32) * TSTRIDE;

        float acc[RPB];
        #pragma unroll
        for (int rr = 0; rr < RPB; rr++) acc[rr] = 0.f;

        #pragma unroll 4
        for (int kk = 0; kk < 32; kk++) {
            float wu = w[(size_t)kk * HID];
            const float* row = tb + kk * TSTRIDE;
            float4 rA = *(const float4*)(row);       // rows 0..3 (bcast)
            float4 rB = *(const float4*)(row + 4);   // rows 4..7
            acc[0] = fmaf(rA.x, wu, acc[0]);
            acc[1] = fmaf(rA.y, wu, acc[1]);
            acc[2] = fmaf(rA.z, wu, acc[2]);
            acc[3] = fmaf(rA.w, wu, acc[3]);
            acc[4] = fmaf(rB.x, wu, acc[4]);
            acc[5] = fmaf(rB.y, wu, acc[5]);
            acc[6] = fmaf(rB.z, wu, acc[6]);
            acc[7] = fmaf(rB.w, wu, acc[7]);
        }
        #pragma unroll
        for (int rr = 0; rr < RPB; rr++)
            part[(c * RPB + rr) * PSTRIDE + o] = acc[rr];
    }
    __syncthreads();

    // reduce 8 chunks; TRANSPOSED store to g_paT/g_pbT[k][node]
    {
        int rr = t & 7, oo = t >> 3;
        int r = r0 + rr;
        if (r < N_NODES) {
            float s = 0.f;
            #pragma unroll
            for (int cc = 0; cc < 8; cc++)
                s += part[(cc * RPB + rr) * PSTRIDE + oo];
            int hh = oo >> 6, occ = oo & 63;
            if (hh == 0) g_paT[(size_t)occ * N_NODES + r] = s;
            else         g_pbT[(size_t)occ * N_NODES + r] = s;
        }
    }
}

// =====================================================================
// Edge kernel (fp16x2 math): blocks 0..527 = upper-tri 64x64 tiles;
// blocks 528..543 = trig fixup. 256 threads, per-thread 4i x 4j.
// LDS diet vs R12: a/b pair loads merged into uint2 (LDS.64), w batched
// as one LDS.128 per 4 k. Math/layout/numerics identical to R12.
// =====================================================================
#define TILE 64
#define HPAD 72                       // half-row stride (144B, 8B-aligned)
#define NT   (N_NODES / TILE)         // 32
#define NTILES (NT * (NT + 1) / 2)    // 528
#define NFIX 16

__global__ __launch_bounds__(256) void edge_kernel(const float* __restrict__ ew2,
                                                   const float* __restrict__ eb2,
                                                   float* __restrict__ trig_out,
                                                   float* __restrict__ out) {
    int m = blockIdx.x;
    int tid = threadIdx.x;

    if (m >= NTILES) {
        // -------- trig fixup: trig[10:][:] += h3 (float4) --------
        int f = m - NTILES;                                  // 0..15
        const int total4 = (N_NODES - TEMPLATE) * FDIM / 4;  // 130432
        const int per = (total4 + NFIX - 1) / NFIX;
        int s = f * per;
        int e = s + per; if (e > total4) e = total4;
        float4* base = (float4*)(trig_out + (size_t)TEMPLATE * FDIM);
        for (int i = s + tid; i < e; i += 256) {
            int c4 = i & 63;
            float4 h = __ldg((const float4*)&g_h3[c4 * 4]);
            float4 v = base[i];
            v.x += h.x; v.y += h.y; v.z += h.z; v.w += h.w;
            base[i] = v;
        }
        return;
    }

    // decode (bi, bj) with bj >= bi from m
    int bi = (int)(32.5f - sqrtf(32.5f * 32.5f - 2.0f * (float)m));
    while (bi * NT - ((bi * (bi - 1)) >> 1) > m) bi--;
    while ((bi + 1) * NT - (((bi + 1) * bi) >> 1) <= m) bi++;
    int bj = bi + (m - (bi * NT - ((bi * (bi - 1)) >> 1)));

    __shared__ __half pah[HID][HPAD];     // [k][i], +ha folded
    __shared__ __half pbh[HID][HPAD];     // [k][j], +hb folded
    __shared__ __half2 w2h[HID];          // (w,w) pairs, 16B-aligned

    // tile load: g_paT/g_pbT are [k][node] float; convert to half
    {
        const float* paG = g_paT + (size_t)bi * TILE;
        const float* pbG = g_pbT + (size_t)bj * TILE;
        #pragma unroll
        for (int it = 0; it < 4; it++) {
            int idx = tid + it * 256;     // 1024 slots: k = idx>>4, c4
            int k = idx >> 4;
            int c4 = (idx & 15) << 2;
            float hav = __ldg(&g_ha[k]);
            float hbv = __ldg(&g_hb[k]);
            float4 va = *(const float4*)(paG + (size_t)k * N_NODES + c4);
            __half2 pa01 = __floats2half2_rn(va.x + hav, va.y + hav);
            __half2 pa23 = __floats2half2_rn(va.z + hav, va.w + hav);
            *(__half2*)&pah[k][c4]     = pa01;
            *(__half2*)&pah[k][c4 + 2] = pa23;
            float4 vb = *(const float4*)(pbG + (size_t)k * N_NODES + c4);
            __half2 pb01 = __floats2half2_rn(vb.x + hbv, vb.y + hbv);
            __half2 pb23 = __floats2half2_rn(vb.z + hbv, vb.w + hbv);
            *(__half2*)&pbh[k][c4]     = pb01;
            *(__half2*)&pbh[k][c4 + 2] = pb23;
        }
        if (tid < HID) w2h[tid] = __float2half2_rn(ew2[tid]);
    }
    float c0 = eb2[0];
    __syncthreads();

    int tx = tid & 15;   // j-group: j = 4*tx + (0..3)
    int ty = tid >> 4;   // i-group: i = 4*ty + (0..3)

    const __half2 zero2 = __float2half2_rn(0.0f);
    // acc[group][i][jp]: 4 interleaved 16-term fp16 partial sums
    __half2 acc[4][4][2];
    #pragma unroll
    for (int g = 0; g < 4; g++)
        #pragma unroll
        for (int i = 0; i < 4; i++) {
            acc[g][i][0] = zero2;
            acc[g][i][1] = zero2;
        }

    #pragma unroll
    for (int k4 = 0; k4 < HID; k4 += 4) {
        // 4 w pairs in one LDS.128 (w2h is 16B-aligned, k4*4B stride)
        uint4 wq = *(const uint4*)&w2h[k4];
        #pragma unroll
        for (int kk = 0; kk < 4; kk++) {
            int k = k4 + kk;
            int g = kk;                               // == k & 3
            unsigned wbits = (kk == 0) ? wq.x : (kk == 1) ? wq.y
                           : (kk == 2) ? wq.z : wq.w;
            __half2 wk = *(__half2*)&wbits;
            // a pair (a01,a23) in one LDS.64; likewise b
            uint2 au = *(const uint2*)&pah[k][4 * ty];
            uint2 bu = *(const uint2*)&pbh[k][4 * tx];
            __half2 a01 = *(__half2*)&au.x;
            __half2 a23 = *(__half2*)&au.y;
            __half2 b01 = *(__half2*)&bu.x;
            __half2 b23 = *(__half2*)&bu.y;
            __half2 ai[4];
            ai[0] = __lows2half2(a01, a01);
            ai[1] = __highs2half2(a01, a01);
            ai[2] = __lows2half2(a23, a23);
            ai[3] = __highs2half2(a23, a23);
            #pragma unroll
            for (int i = 0; i < 4; i++) {
                __half2 s0 = __hmax2(__hadd2(ai[i], b01), zero2);
                __half2 s1 = __hmax2(__hadd2(ai[i], b23), zero2);
                acc[g][i][0] = __hfma2(s0, wk, acc[g][i][0]);
                acc[g][i][1] = __hfma2(s1, wk, acc[g][i][1]);
            }
        }
    }

    int ibase = bi * TILE;
    int jbase = bj * TILE;
    #pragma unroll
    for (int i = 0; i < 4; i++) {
        int ii = ibase + 4 * ty + i;
        int off = ii * (N_NODES - 1) - ((ii * (ii - 1)) >> 1) - ii - 1;
        #pragma unroll
        for (int jp = 0; jp < 2; jp++) {
            float2 s = make_float2(0.f, 0.f);
            #pragma unroll
            for (int g = 0; g < 4; g++) {
                float2 p = __half22float2(acc[g][i][jp]);
                s.x += p.x; s.y += p.y;
            }
            int j0 = jbase + 4 * tx + 2 * jp;
            if (j0     > ii) out[off + j0]     = sigmoid_fast(s.x + c0);
            if (j0 + 1 > ii) out[off + j0 + 1] = sigmoid_fast(s.y + c0);
        }
    }
}

// =====================================================================
// Launch
// =====================================================================
extern "C" void kernel_launch(void* const* d_in, const int* in_sizes, int n_in,
                              void* d_out, int out_size) {
    const float* clean_features = (const float*)d_in[0];
    const int*   selected_nodes = (const int*)  d_in[1];
    const float* noise          = (const float*)d_in[2];
    const float* gcn1_w         = (const float*)d_in[3];
    const float* gcn1_b         = (const float*)d_in[4];
    const float* gcn2_w         = (const float*)d_in[5];
    const float* gcn2_b         = (const float*)d_in[6];
    const float* gcn3_w         = (const float*)d_in[7];
    const float* gcn3_b         = (const float*)d_in[8];
    const float* ew1            = (const float*)d_in[9];
    const float* eb1            = (const float*)d_in[10];
    const float* ew2            = (const float*)d_in[11];
    const float* eb2            = (const float*)d_in[12];

    float* out = (float*)d_out;
    float* trig_out = out;                    // [2048, 256]
    float* edge_out = out + N_NODES * FDIM;   // [2096128]

    cudaFuncSetAttribute(merged_kernel,
                         cudaFuncAttributeMaxDynamicSharedMemorySize,
                         SMEM_BYTES);

    // 1 gcn(+hab) block + 255 noise blocks; 88.6KB smem + 32-reg cap
    merged_kernel<<<256, 1024, SMEM_BYTES>>>(
        clean_features, selected_nodes,
        gcn1_w, gcn1_b, gcn2_w, gcn2_b, gcn3_w, gcn3_b,
        noise, ew1, eb1, trig_out);

    edge_kernel<<<NTILES + NFIX, 256>>>(ew2, eb2, trig_out, edge_out);
}